// round 6
// baseline (speedup 1.0000x reference)
#include <cuda_runtime.h>
#include <cstdint>

#define THREADS 512

// ---- problem constants ----
#define Cc    4
#define Tt    1000
#define FQn   1025
#define Dd    384
#define INF   128      // W*C
#define Mrows 8000     // B*T
#define KB    45

// ---- tiling ----
#define MT    256      // rows per CTA (16 warps x 16 rows)
#define DC    32       // D chunk
#define NCH   (Dd / DC)   // 12

// ---- smem layout (uint32 units), everything stored in MMA fragment order ----
#define OFF_X   0
#define SZ_X    (16*16*128)     // 16 m-tiles x 16 k-tiles
#define OFF_WP  (OFF_X + SZ_X)
#define SZ_WP   (16*2*128)      // 16 k-tiles x 2 n-pairs
#define OFF_WQ  (OFF_WP + SZ_WP)
#define SZ_WQ   (4*8*128)       // 4 k-tiles x 8 n-pairs
#define OFF_H   (OFF_WQ + SZ_WQ)
#define SZ_H    (16*4*128)      // 16 m-tiles x 4 k-tiles
#define SMEM_U32 (OFF_H + SZ_H)      // 49152 u32 = 192 KB

// Band tables (disjoint frequency groups)
__constant__ int c_start[KB] = {
    0,4,9,15,22,30,39,49,60,72,85,99,114,130,147,165,184,204,225,247,
    270,294,319,345,372,400,429,459,490,522,554,586,618,650,682,714,
    746,778,810,842,874,906,938,970,1002};
__constant__ int c_width[KB] = {
    4,5,6,7,8,9,10,11,12,13,14,15,16,17,18,19,20,21,22,23,
    24,25,26,27,28,29,30,31,32,32,32,32,32,32,32,32,
    32,32,32,32,32,32,32,32,23};

__device__ __forceinline__ uint32_t f2tf(float f) {
    uint32_t r;
    asm("cvt.rna.tf32.f32 %0, %1;" : "=r"(r) : "f"(f));
    return r;
}

__device__ __forceinline__ void mma8(float* c, const uint4 a, uint32_t b0, uint32_t b1) {
    asm volatile(
        "mma.sync.aligned.m16n8k8.row.col.f32.tf32.tf32.f32 "
        "{%0,%1,%2,%3},{%4,%5,%6,%7},{%8,%9},{%0,%1,%2,%3};"
        : "+f"(c[0]), "+f"(c[1]), "+f"(c[2]), "+f"(c[3])
        : "r"(a.x), "r"(a.y), "r"(a.z), "r"(a.w), "r"(b0), "r"(b1));
}

__global__ __launch_bounds__(THREADS, 1)
void bandsplit_mma(const float* __restrict__ x,
                   const float* __restrict__ w_pre,
                   const float* __restrict__ b_pre,
                   const float* __restrict__ w_post,
                   const float* __restrict__ b_post,
                   float* __restrict__ out)
{
    extern __shared__ uint32_t sm[];
    __shared__ float bpre_sh[DC];
    __shared__ float bpost_sh[INF];

    const int k     = blockIdx.y;
    const int tile0 = blockIdx.x * MT;
    const int tid   = threadIdx.x;
    const int warp  = tid >> 5;      // 0..15, == m-tile index
    const int lane  = tid & 31;
    const int fs    = c_start[k];
    const int fw    = c_width[k];

    // band-sparsity limits (uniform across CTA)
    const int kt_lim = (fw + 1) >> 1;   // GEMM1 K-tiles with any valid kk (kk = w*4+c < 4*fw)
    const int np_lim = (fw + 3) >> 2;   // GEMM2 N-pairs with any valid o (o < 4*fw)
    const int nt_lim = kt_lim;          // valid output n-tiles (o-tiles of 8): ceil(4*fw/8)

    for (int i = tid; i < INF; i += THREADS) bpost_sh[i] = b_post[k * INF + i];

    // ---- gather X into A-fragment layout (tf32) ----
    // one warp per (m, channel): lanes read 32 consecutive freqs (coalesced 128B)
    for (int task = warp; task < MT * Cc; task += 16) {
        const int m  = task >> 2;
        const int c  = task & 3;
        const int mg = tile0 + m;
        const int w  = lane;
        float v = 0.0f;
        if (mg < Mrows && w < fw) {
            const int b = mg / Tt;
            const int t = mg - b * Tt;
            v = x[((size_t)(b * Cc + c) * Tt + t) * FQn + fs + w];
        }
        // kk = w*4 + c ; A-frag addressing
        const int kt     = w >> 1;
        const int gm     = m >> 4;
        const int lane_s = ((m & 7) << 2) | c;
        const int reg    = ((w & 1) << 1) | ((m >> 3) & 1);
        sm[OFF_X + (((gm * 16 + kt) * 32 + lane_s) << 2) + reg] = f2tf(v);
    }

    // GEMM2 accumulators: 16 n-tiles x 4 regs (only nt < nt_lim used, init all)
    float yacc[16][4];
    #pragma unroll
    for (int nt = 0; nt < 16; ++nt)
        #pragma unroll
        for (int e = 0; e < 4; ++e) yacc[nt][e] = 0.0f;

    for (int ch = 0; ch < NCH; ++ch) {
        const int dbase = ch * DC;
        __syncthreads();   // previous chunk's MMA reads of WP/WQ/H complete

        // ---- stage w_pre chunk: only valid kk rows (kk < kt_lim*8) ----
        {
            const int nrows = kt_lim * 8;
            for (int i = tid; i < nrows * 32; i += THREADS) {
                const int kk = i >> 5;
                const int d  = i & 31;
                const float v = w_pre[((size_t)k * INF + kk) * Dd + dbase + d];
                const int kt = kk >> 3, kr = kk & 7, nt = d >> 3, nc = d & 7;
                const int np = nt >> 1, p = nt & 1;
                const int lane_s = (nc << 2) | (kr & 3);
                const int reg    = (p << 1) | (kr >> 2);
                sm[OFF_WP + (((kt * 2 + np) * 32 + lane_s) << 2) + reg] = f2tf(v);
            }
        }
        // ---- stage w_post chunk: only valid o columns (o < np_lim*16) ----
        {
            const int olim = np_lim * 16;
            for (int i = tid; i < DC * INF; i += THREADS) {
                const int o = i & 127;
                if (o < olim) {
                    const int d = i >> 7;
                    const float v = w_post[((size_t)k * Dd + dbase + d) * INF + o];
                    const int kt = d >> 3, kr = d & 7, nt = o >> 3, nc = o & 7;
                    const int np = nt >> 1, p = nt & 1;
                    const int lane_s = (nc << 2) | (kr & 3);
                    const int reg    = (p << 1) | (kr >> 2);
                    sm[OFF_WQ + (((kt * 8 + np) * 32 + lane_s) << 2) + reg] = f2tf(v);
                }
            }
        }
        if (tid < DC) bpre_sh[tid] = b_pre[k * Dd + dbase + tid];
        __syncthreads();

        // ---- GEMM1: H[16 x DC] per warp, K limited to valid tiles ----
        float h[4][4];
        #pragma unroll
        for (int nt = 0; nt < 4; ++nt)
            #pragma unroll
            for (int e = 0; e < 4; ++e) h[nt][e] = 0.0f;

        {
            const uint4* XF  = (const uint4*)(sm + OFF_X);
            const uint4* WpF = (const uint4*)(sm + OFF_WP);
            for (int kt = 0; kt < kt_lim; ++kt) {
                const uint4 a = XF[(warp * 16 + kt) * 32 + lane];
                #pragma unroll
                for (int np = 0; np < 2; ++np) {
                    const uint4 b = WpF[(kt * 2 + np) * 32 + lane];
                    mma8(h[np * 2],     a, b.x, b.y);
                    mma8(h[np * 2 + 1], a, b.z, b.w);
                }
            }
        }

        // ---- repack H (+b_pre, tf32) into GEMM2 A-fragment layout (warp-private) ----
        #pragma unroll
        for (int e = 0; e < 4; ++e) {
            const int lane2 = (lane & 0x1C) | ((lane & 1) << 1) | (e & 1);
            const int reg2  = (((lane >> 1) & 1) << 1) | (e >> 1);
            const int col   = ((lane & 3) << 1) | (e & 1);
            #pragma unroll
            for (int nt = 0; nt < 4; ++nt) {   // nt == k-tile of GEMM2 (D dense)
                const int d = nt * 8 + col;
                const float v = h[nt][e] + bpre_sh[d];
                sm[OFF_H + (((warp * 4 + nt) * 32 + lane2) << 2) + reg2] = f2tf(v);
            }
        }
        __syncwarp();

        // ---- GEMM2: Y[16 x olim] += H[16 x DC] * Wpost[DC x olim] ----
        {
            const uint4* HF  = (const uint4*)(sm + OFF_H);
            const uint4* WqF = (const uint4*)(sm + OFF_WQ);
            #pragma unroll
            for (int kt = 0; kt < 4; ++kt) {
                const uint4 a = HF[(warp * 4 + kt) * 32 + lane];
                for (int np = 0; np < np_lim; ++np) {
                    const uint4 b = WqF[(kt * 8 + np) * 32 + lane];
                    mma8(yacc[np * 2],     a, b.x, b.y);
                    mma8(yacc[np * 2 + 1], a, b.z, b.w);
                }
            }
        }
    }

    // ---- epilogue: stage Y in smem (reuse X/WP region), then coalesced scatter ----
    __syncthreads();
    float* Ybuf = (float*)sm;   // [m][c][w] : m stride 132, c stride 33
    #pragma unroll
    for (int e = 0; e < 4; ++e) {
        const int r   = (lane >> 2) + ((e >> 1) << 3);
        const int col = ((lane & 3) << 1) | (e & 1);
        const int m   = warp * 16 + r;
        for (int nt = 0; nt < nt_lim; ++nt) {
            const int o = nt * 8 + col;
            Ybuf[m * 132 + (o & 3) * 33 + (o >> 2)] = yacc[nt][e] + bpost_sh[o];
        }
    }
    __syncthreads();

    for (int task = warp; task < MT * Cc; task += 16) {
        const int m  = task >> 2;
        const int c  = task & 3;
        const int mg = tile0 + m;
        const int w  = lane;
        if (mg < Mrows && w < fw) {
            const int b = mg / Tt;
            const int t = mg - b * Tt;
            out[((size_t)(b * Cc + c) * Tt + t) * FQn + fs + w] = Ybuf[m * 132 + c * 33 + w];
        }
    }
}

extern "C" void kernel_launch(void* const* d_in, const int* in_sizes, int n_in,
                              void* d_out, int out_size)
{
    (void)in_sizes; (void)n_in; (void)out_size;
    const float* x      = (const float*)d_in[0];
    const float* w_pre  = (const float*)d_in[1];
    const float* b_pre  = (const float*)d_in[2];
    const float* w_post = (const float*)d_in[3];
    const float* b_post = (const float*)d_in[4];
    float* out = (float*)d_out;

    const size_t smem_bytes = (size_t)SMEM_U32 * sizeof(uint32_t);  // 192 KB
    cudaFuncSetAttribute(bandsplit_mma,
                         cudaFuncAttributeMaxDynamicSharedMemorySize,
                         (int)smem_bytes);

    dim3 grid((Mrows + MT - 1) / MT, KB);   // (32, 45)
    bandsplit_mma<<<grid, THREADS, smem_bytes>>>(x, w_pre, b_pre, w_post, b_post, out);
}